// round 17
// baseline (speedup 1.0000x reference)
#include <cuda_runtime.h>
#include <math.h>

#define BB 64
#define MM 2048
#define CC 64
#define HH 128
#define NNZE 32768
#define H3 384
#define PADN 40960
#define HALFE 16384

// -------- scratch (static device arrays; no runtime malloc) --------
__device__ int           g_h[2][BB*MM];     // per-half row histograms
__device__ int           g_curb[2][BB*MM];  // per-half scatter cursor bases
__device__ int           g_cluscnt[BB*CC];
__device__ int           g_clusoff[BB*CC];
__device__ int           g_csplit[BB*CC*4];
__device__ unsigned char g_nit[BB*MM];
__device__ int2          g_csr[BB*PADN];
__device__ float         g_xdec[BB*CC*H3];
__device__ float         g_qkv2[2][3][BB*CC*HH];  // [K-half][Q/K/V]

// ============ K1a: per-half row histograms (128 CTAs, smem atomics) ======
__global__ void __launch_bounds__(1024) k_hist2(const int* __restrict__ rows) {
    __shared__ int hist[MM];
    int g = blockIdx.x >> 1, half = blockIdx.x & 1;
    int tid = threadIdx.x;
    hist[tid] = 0; hist[tid + 1024] = 0;
    __syncthreads();
    const int* r = rows + g * NNZE + half * HALFE;
    for (int i = tid; i < HALFE; i += 1024) atomicAdd(&hist[r[i]], 1);
    __syncthreads();
    g_h[half][g*MM + tid]        = hist[tid];
    g_h[half][g*MM + tid + 1024] = hist[tid + 1024];
}

// ============ K1b: cluster ordering + padded scan + cursors/metadata =====
__global__ void __launch_bounds__(1024) k_build(const int* __restrict__ idx) {
    __shared__ short pos2row[MM];
    __shared__ int   ss[1024];
    __shared__ int   curs[MM];
    __shared__ int   chist[CC], ccur[CC], coffs[CC];
    int g = blockIdx.x, tid = threadIdx.x;
    if (tid < CC) chist[tid] = 0;
    __syncthreads();

    const int* ix = idx + g * MM;
    int i0 = __ldg(&ix[tid]), i1 = __ldg(&ix[tid + 1024]);
    atomicAdd(&chist[i0], 1);
    atomicAdd(&chist[i1], 1);
    __syncthreads();

    if (tid == 0) {
        int acc = 0;
        for (int c = 0; c < CC; c++) {
            coffs[c] = acc; ccur[c] = acc;
            g_clusoff[g*CC + c] = acc;
            g_cluscnt[g*CC + c] = chist[c];
            acc += chist[c];
        }
    }
    __syncthreads();

    int p0 = atomicAdd(&ccur[i0], 1); pos2row[p0] = (short)tid;
    int p1 = atomicAdd(&ccur[i1], 1); pos2row[p1] = (short)(tid + 1024);
    __syncthreads();

    int r0 = pos2row[2*tid], r1 = pos2row[2*tid + 1];
    int h00 = g_h[0][g*MM + r0], h10 = g_h[1][g*MM + r0];
    int h01 = g_h[0][g*MM + r1], h11 = g_h[1][g*MM + r1];
    int len0 = h00 + h10, len1 = h01 + h11;
    int l0 = (len0 + 3) & ~3, l1 = (len1 + 3) & ~3;
    int t = l0 + l1;
    ss[tid] = t;
    __syncthreads();
    for (int off = 1; off < 1024; off <<= 1) {
        int v = (tid >= off) ? ss[tid - off] : 0;
        __syncthreads();
        ss[tid] += v;
        __syncthreads();
    }
    int excl = ss[tid] - t;
    int o0 = excl, o1 = excl + l0;
    curs[r0] = o0;  curs[r1] = o1;
    g_curb[0][g*MM + r0] = o0;         g_curb[1][g*MM + r0] = o0 + h00;
    g_curb[0][g*MM + r1] = o1;         g_curb[1][g*MM + r1] = o1 + h01;
    g_nit[g*MM + 2*tid]     = (unsigned char)(l0 >> 2);
    g_nit[g*MM + 2*tid + 1] = (unsigned char)(l1 >> 2);

    int2* cbase = g_csr + (size_t)g * PADN;
    for (int k = len0; k < l0; k++) cbase[o0 + k] = make_int2(0, 0);
    for (int k = len1; k < l1; k++) cbase[o1 + k] = make_int2(0, 0);
    __syncthreads();

    if (tid < CC) {
        int cp = coffs[tid], nr = chist[tid];
        #pragma unroll
        for (int q = 0; q < 4; q++) {
            int qs = (nr * q) >> 2;
            g_csplit[(g*CC + tid)*4 + q] =
                (nr > 0) ? curs[pos2row[cp + qs]] : 0;
        }
    }
}

// ============ K1c: scatter edges (128 CTAs, smem cursors) ================
__global__ void __launch_bounds__(1024) k_scatter2(const int* __restrict__ rows,
                                                   const int* __restrict__ cols,
                                                   const float* __restrict__ vals) {
    __shared__ int cur[MM];
    int g = blockIdx.x >> 1, half = blockIdx.x & 1;
    int tid = threadIdx.x;
    const int* cb = g_curb[half] + g * MM;
    cur[tid]        = cb[tid];
    cur[tid + 1024] = cb[tid + 1024];
    __syncthreads();
    int base = g * NNZE + half * HALFE;
    const int*   r = rows + base;
    const int*   c = cols + base;
    const float* v = vals + base;
    int2* cbase = g_csr + (size_t)g * PADN;
    for (int i = tid; i < HALFE; i += 1024) {
        int rr = r[i];
        int p = atomicAdd(&cur[rr], 1);
        cbase[p] = make_int2(c[i], __float_as_int(v[i]));
    }
}

// ============ K2: SpMM + pooling (R7; at the L2 traffic floor) ===========
__global__ void __launch_bounds__(256) k_spmm(const float4* __restrict__ x4) {
    __shared__ float comb[2][3][32][8];
    int g = blockIdx.x >> 5;
    int cgrp = blockIdx.x & 31;
    int wid = threadIdx.x >> 5, lane = threadIdx.x & 31;
    int ci = wid >> 2;
    int sub = wid & 3;
    int c = cgrp * 2 + ci;
    int nr  = g_cluscnt[g*CC + c];
    int pos = g_clusoff[g*CC + c];
    int lo = (nr * sub) >> 2, hi = (nr * (sub + 1)) >> 2;
    int eptr = g_csplit[(g*CC + c)*4 + sub];
    const float4* xq = x4 + (size_t)g * MM * 32;
    const int4* cs = (const int4*)(g_csr + (size_t)g * PADN + eptr);
    const unsigned char* nitp = g_nit + g * MM + pos;

    float4 s  = make_float4(0.f, 0.f, 0.f, 0.f);
    float4 mx = make_float4(-INFINITY, -INFINITY, -INFINITY, -INFINITY);

    for (int j0 = lo; j0 < hi; j0 += 32) {
        int lim = min(32, hi - j0);
        int myv = (lane < lim) ? (int)nitp[j0 + lane] : 0;
        for (int j = 0; j < lim; j++) {
            int it = __shfl_sync(0xFFFFFFFFu, myv, j);
            float4 acc = make_float4(0.f, 0.f, 0.f, 0.f);
            #pragma unroll 2
            for (int t = 0; t < it; t++) {
                int4 a = __ldg(cs);
                int4 b = __ldg(cs + 1);
                cs += 2;
                float4 v0 = __ldg(&xq[a.x * 32 + lane]);
                float4 v1 = __ldg(&xq[a.z * 32 + lane]);
                float4 v2 = __ldg(&xq[b.x * 32 + lane]);
                float4 v3 = __ldg(&xq[b.z * 32 + lane]);
                float f0 = __int_as_float(a.y), f1 = __int_as_float(a.w);
                float f2 = __int_as_float(b.y), f3 = __int_as_float(b.w);
                acc.x += f0*v0.x + f1*v1.x + f2*v2.x + f3*v3.x;
                acc.y += f0*v0.y + f1*v1.y + f2*v2.y + f3*v3.y;
                acc.z += f0*v0.z + f1*v1.z + f2*v2.z + f3*v3.z;
                acc.w += f0*v0.w + f1*v1.w + f2*v2.w + f3*v3.w;
            }
            s.x += acc.x; s.y += acc.y; s.z += acc.z; s.w += acc.w;
            mx.x = fmaxf(mx.x, acc.x); mx.y = fmaxf(mx.y, acc.y);
            mx.z = fmaxf(mx.z, acc.z); mx.w = fmaxf(mx.w, acc.w);
        }
    }
    if (sub != 0) {
        float* cb = comb[ci][sub - 1][lane];
        cb[0] = s.x;  cb[1] = s.y;  cb[2] = s.z;  cb[3] = s.w;
        cb[4] = mx.x; cb[5] = mx.y; cb[6] = mx.z; cb[7] = mx.w;
    }
    __syncthreads();
    if (sub == 0) {
        #pragma unroll
        for (int w = 0; w < 3; w++) {
            const float* cb = comb[ci][w][lane];
            s.x += cb[0]; s.y += cb[1]; s.z += cb[2]; s.w += cb[3];
            mx.x = fmaxf(mx.x, cb[4]); mx.y = fmaxf(mx.y, cb[5]);
            mx.z = fmaxf(mx.z, cb[6]); mx.w = fmaxf(mx.w, cb[7]);
        }
        float cf = fmaxf((float)nr, 1.f);
        float* xd = g_xdec + (g*CC + c) * H3;
        float4 mean = make_float4(s.x/cf, s.y/cf, s.z/cf, s.w/cf);
        *(float4*)&xd[lane*4]        = mean;
        *(float4*)&xd[HH + lane*4]   = mx;
        *(float4*)&xd[2*HH + lane*4] = s;
    }
}

// ============ packed f32x2 helpers ============
__device__ __forceinline__ void ffma2(unsigned long long& d,
                                      unsigned long long a,
                                      unsigned long long b) {
    asm("fma.rn.f32x2 %0, %1, %2, %0;" : "+l"(d) : "l"(a), "l"(b));
}
__device__ __forceinline__ unsigned long long pack2(float v) {
    unsigned long long r;
    asm("mov.b64 %0, {%1, %1};" : "=l"(r) : "f"(v));
    return r;
}

// ============ K3: Q/K/V GEMM, grid (64,3,2Khalf x 2Nhalf), 128 thr =======
// 768 CTAs -> 5.2 CTAs/SM (~21 warps/SM) to hide LDS latency; 4x8 microtile
// keeps the B-traffic ratio of R16 (32B per 16 FFMA2) with R8-style
// transposed-A LDS.128 reads. K-half partials summed in attn staging.
#define XS_LD 68
__global__ void __launch_bounds__(128) k_gemm(const float* __restrict__ Wq,
                                              const float* __restrict__ Wk,
                                              const float* __restrict__ Wv) {
    extern __shared__ float sm[];
    float* xsA = sm;                // [64 kk][68 pad] transposed A tile
    float* Bs  = sm + 64 * XS_LD;   // [64 kk][64 col] W half-tile
    int g = blockIdx.x, which = blockIdx.y;
    int kh = blockIdx.z >> 1, nh = blockIdx.z & 1;
    const float* W = ((which == 0) ? Wq : (which == 1) ? Wk : Wv) + nh * 64;
    float* out = g_qkv2[kh][which] + g * CC * HH + nh * 64;
    const float* xd = g_xdec + g * CC * H3 + kh * 192;
    int tid = threadIdx.x;
    int ty = tid >> 3, tx = tid & 7;   // 16 row-groups x 8 col-groups

    unsigned long long acc[4][4];
    #pragma unroll
    for (int i = 0; i < 4; i++)
        #pragma unroll
        for (int j = 0; j < 4; j++) acc[i][j] = 0ull;

    for (int kt = 0; kt < 192; kt += 64) {
        __syncthreads();
        // A: transpose staging (coalesced LDG: consecutive tid -> consec kk)
        for (int i = tid; i < 64 * 64; i += 128) {
            int kk = i & 63, row = i >> 6;
            xsA[kk * XS_LD + row] = xd[row * H3 + kt + kk];
        }
        // B tile [64 kk][64 col]
        for (int i = tid; i < 64 * 16; i += 128) {
            int row = i >> 4, c4 = i & 15;
            *(float4*)&Bs[row * 64 + c4 * 4] =
                __ldg((const float4*)&W[(kh * 192 + kt + row) * HH + c4 * 4]);
        }
        __syncthreads();
        #pragma unroll 8
        for (int kk = 0; kk < 64; kk++) {
            float4 av = *(const float4*)&xsA[kk * XS_LD + ty * 4];
            const float* wb = &Bs[kk * 64 + tx * 8];
            ulonglong2 b01 = *(const ulonglong2*)wb;
            ulonglong2 b23 = *(const ulonglong2*)(wb + 4);
            unsigned long long pa0 = pack2(av.x), pa1 = pack2(av.y);
            unsigned long long pa2 = pack2(av.z), pa3 = pack2(av.w);
            ffma2(acc[0][0], pa0, b01.x); ffma2(acc[0][1], pa0, b01.y);
            ffma2(acc[0][2], pa0, b23.x); ffma2(acc[0][3], pa0, b23.y);
            ffma2(acc[1][0], pa1, b01.x); ffma2(acc[1][1], pa1, b01.y);
            ffma2(acc[1][2], pa1, b23.x); ffma2(acc[1][3], pa1, b23.y);
            ffma2(acc[2][0], pa2, b01.x); ffma2(acc[2][1], pa2, b01.y);
            ffma2(acc[2][2], pa2, b23.x); ffma2(acc[2][3], pa2, b23.y);
            ffma2(acc[3][0], pa3, b01.x); ffma2(acc[3][1], pa3, b01.y);
            ffma2(acc[3][2], pa3, b23.x); ffma2(acc[3][3], pa3, b23.y);
        }
    }
    #pragma unroll
    for (int i = 0; i < 4; i++) {
        ulonglong2 o0; o0.x = acc[i][0]; o0.y = acc[i][1];
        ulonglong2 o1; o1.x = acc[i][2]; o1.y = acc[i][3];
        float* orow = &out[(ty*4 + i) * HH + tx * 8];
        *(ulonglong2*)orow       = o0;
        *(ulonglong2*)(orow + 4) = o1;
    }
}

// ============ K4: attention; staging sums the two K-half partials ========
__global__ void __launch_bounds__(256) k_attn(float* __restrict__ out) {
    extern __shared__ float sm[];
    float* Qs = sm;                   // 16 * 132
    float* Ks = Qs + 16 * 132;        // 64 * 132
    float* Vs = Ks + 64 * 132;        // 64 * 132
    float* Ss = Vs + 64 * 132;        // 16 * 68
    int g = blockIdx.x, rh = blockIdx.y * 16, tid = threadIdx.x;
    const float4* Qg0 = (const float4*)(g_qkv2[0][0] + g * CC * HH + rh * HH);
    const float4* Qg1 = (const float4*)(g_qkv2[1][0] + g * CC * HH + rh * HH);
    const float4* Kg0 = (const float4*)(g_qkv2[0][1] + g * CC * HH);
    const float4* Kg1 = (const float4*)(g_qkv2[1][1] + g * CC * HH);
    const float4* Vg0 = (const float4*)(g_qkv2[0][2] + g * CC * HH);
    const float4* Vg1 = (const float4*)(g_qkv2[1][2] + g * CC * HH);

    for (int i = tid; i < 16 * 32; i += 256) {
        int r = i >> 5, cc = i & 31;
        float4 a = __ldg(&Qg0[r * 32 + cc]);
        float4 b = __ldg(&Qg1[r * 32 + cc]);
        ((float4*)Qs)[r * 33 + cc] =
            make_float4(a.x+b.x, a.y+b.y, a.z+b.z, a.w+b.w);
    }
    for (int i = tid; i < 64 * 32; i += 256) {
        int r = i >> 5, cc = i & 31;
        float4 a = __ldg(&Kg0[r * 32 + cc]);
        float4 b = __ldg(&Kg1[r * 32 + cc]);
        ((float4*)Ks)[r * 33 + cc] =
            make_float4(a.x+b.x, a.y+b.y, a.z+b.z, a.w+b.w);
        float4 c = __ldg(&Vg0[r * 32 + cc]);
        float4 d = __ldg(&Vg1[r * 32 + cc]);
        ((float4*)Vs)[r * 33 + cc] =
            make_float4(c.x+d.x, c.y+d.y, c.z+d.z, c.w+d.w);
    }
    __syncthreads();

    int r = tid & 15, grp = tid >> 4;
    {
        float sacc[4] = {0.f, 0.f, 0.f, 0.f};
        const float4* q4 = (const float4*)Qs + r * 33;
        const float4* k4 = (const float4*)Ks;
        #pragma unroll 4
        for (int h4 = 0; h4 < 32; h4++) {
            float4 q = q4[h4];
            #pragma unroll
            for (int cc = 0; cc < 4; cc++) {
                float4 k = k4[(grp*4 + cc) * 33 + h4];
                sacc[cc] += q.x*k.x + q.y*k.y + q.z*k.z + q.w*k.w;
            }
        }
        const float scale = 0.08838834764831845f;   // 1/sqrt(128)
        #pragma unroll
        for (int cc = 0; cc < 4; cc++) Ss[r*68 + grp*4 + cc] = sacc[cc] * scale;
    }
    __syncthreads();
    {
        int wid = tid >> 5, lane = tid & 31;
        int rr = wid * 2 + (lane >> 4);
        int l16 = lane & 15;
        float v0 = Ss[rr*68 + l16];
        float v1 = Ss[rr*68 + l16 + 16];
        float v2 = Ss[rr*68 + l16 + 32];
        float v3 = Ss[rr*68 + l16 + 48];
        float m = fmaxf(fmaxf(v0, v1), fmaxf(v2, v3));
        #pragma unroll
        for (int o = 1; o < 16; o <<= 1)
            m = fmaxf(m, __shfl_xor_sync(0xFFFFFFFFu, m, o));
        float e0 = __expf(v0 - m), e1 = __expf(v1 - m);
        float e2 = __expf(v2 - m), e3 = __expf(v3 - m);
        float sum = e0 + e1 + e2 + e3;
        #pragma unroll
        for (int o = 1; o < 16; o <<= 1)
            sum += __shfl_xor_sync(0xFFFFFFFFu, sum, o);
        float inv = 1.f / sum;
        Ss[rr*68 + l16]      = e0 * inv;
        Ss[rr*68 + l16 + 16] = e1 * inv;
        Ss[rr*68 + l16 + 32] = e2 * inv;
        Ss[rr*68 + l16 + 48] = e3 * inv;
    }
    __syncthreads();
    {
        float4 a0 = make_float4(0.f,0.f,0.f,0.f), a1 = a0;
        const float4* v4 = (const float4*)Vs;
        #pragma unroll 4
        for (int c = 0; c < CC; c++) {
            float p = Ss[r*68 + c];
            float4 v0 = v4[c * 33 + grp * 2];
            float4 v1 = v4[c * 33 + grp * 2 + 1];
            a0.x += p*v0.x; a0.y += p*v0.y; a0.z += p*v0.z; a0.w += p*v0.w;
            a1.x += p*v1.x; a1.y += p*v1.y; a1.z += p*v1.z; a1.w += p*v1.w;
        }
        float4* o4 = (float4*)out + g * 2048 + (rh + r) * 32 + grp * 2;
        o4[0] = a0; o4[1] = a1;
    }
}

extern "C" void kernel_launch(void* const* d_in, const int* in_sizes, int n_in,
                              void* d_out, int out_size) {
    const float* x    = (const float*)d_in[0];
    const int*   rows = (const int*)d_in[3];
    const int*   cols = (const int*)d_in[4];
    const float* vals = (const float*)d_in[5];
    const int*   idx  = (const int*)d_in[6];
    const float* Wq   = (const float*)d_in[7];
    const float* Wk   = (const float*)d_in[8];
    const float* Wv   = (const float*)d_in[9];
    float* out = (float*)d_out;

    static const int GEMM_SMEM = (64*XS_LD + 64*64) * 4;            // 33792 B
    static const int ATTN_SMEM = ((16 + 2*64) * 132 + 16*68) * 4;   // 80384 B
    cudaFuncSetAttribute(k_gemm, cudaFuncAttributeMaxDynamicSharedMemorySize, GEMM_SMEM);
    cudaFuncSetAttribute(k_attn, cudaFuncAttributeMaxDynamicSharedMemorySize, ATTN_SMEM);

    k_hist2<<<BB * 2, 1024>>>(rows);
    k_build<<<BB, 1024>>>(idx);
    k_scatter2<<<BB * 2, 1024>>>(rows, cols, vals);
    k_spmm<<<BB * 32, 256>>>((const float4*)x);
    k_gemm<<<dim3(BB, 3, 4), 128, GEMM_SMEM>>>(Wq, Wk, Wv);
    k_attn<<<dim3(BB, 4), 256, ATTN_SMEM>>>(out);
}